// round 1
// baseline (speedup 1.0000x reference)
#include <cuda_runtime.h>
#include <math.h>

#define B_  32
#define N_  1024
#define C_  768
#define H_  12
#define D_  64
#define L_  128

// ---------------- scratch (device globals: no allocations allowed) ----------
__device__ float g_Q [B_*N_*C_];        // 25.2M  Q projection (B,N,C)
__device__ float g_xp[B_*L_*C_];        // pooled first-128 tokens
__device__ float g_KV[B_*L_*2*C_];      // K|V projections of pooled tokens
__device__ float g_kf[B_*H_*L_*D_];     // k_full (B,H,128,64)
__device__ float g_vf[B_*H_*L_*D_];     // v_full
__device__ float g_ao[B_*N_*C_];        // attention output (B,N,C)

// ---------------- pooling: xp[b,p,c] = 0.5*(x[b,2p,c]+x[b,2p+1,c]) ----------
__global__ void pool_kernel(const float* __restrict__ x, float* __restrict__ xp)
{
    int i = blockIdx.x * blockDim.x + threadIdx.x;      // float4 index
    const int TOT4 = B_*L_*C_/4;                        // 786432
    if (i >= TOT4) return;
    int c4 = i % (C_/4);
    int p  = (i / (C_/4)) % L_;
    int b  = i / (C_/4 * L_);
    long base = (long)b*N_*C_ + (long)(2*p)*C_ + c4*4;
    float4 a = *reinterpret_cast<const float4*>(x + base);
    float4 c = *reinterpret_cast<const float4*>(x + base + C_);
    float4 o;
    o.x = 0.5f*(a.x+c.x); o.y = 0.5f*(a.y+c.y);
    o.z = 0.5f*(a.z+c.z); o.w = 0.5f*(a.w+c.w);
    *reinterpret_cast<float4*>(xp + (long)i*4) = o;
}

// ---------------- generic 128x128x16 SGEMM, C = A*B + bias ------------------
// A: [M,K] lda, B: [K,N] ldb (row-major), C: [M,N] ldc. All tile-divisible.
__global__ __launch_bounds__(256) void sgemm128(
    const float* __restrict__ A, const float* __restrict__ Bm,
    const float* __restrict__ bias, float* __restrict__ C,
    int K, int lda, int ldb, int ldc)
{
    const int BM = 128, BN = 128, BK = 16;
    __shared__ float As[BK][BM];
    __shared__ float Bs[BK][BN];

    int tid = threadIdx.x;
    int bm = blockIdx.y * BM, bn = blockIdx.x * BN;
    int tx = tid % 16, ty = tid / 16;

    float acc[8][8];
    #pragma unroll
    for (int i = 0; i < 8; i++)
        #pragma unroll
        for (int j = 0; j < 8; j++) acc[i][j] = 0.f;

    int arow = tid >> 2;            // 0..63
    int acol = (tid & 3) * 4;       // 0,4,8,12
    int brow = tid >> 5;            // 0..7
    int bcol = (tid & 31) * 4;      // 0..124

    const float* Aptr = A + (long)(bm + arow) * lda + acol;
    const float* Bptr = Bm + (long)brow * ldb + bn + bcol;

    for (int k0 = 0; k0 < K; k0 += BK) {
        #pragma unroll
        for (int i = 0; i < 2; i++) {
            float4 av = *reinterpret_cast<const float4*>(Aptr + (long)i*64*lda + k0);
            As[acol+0][arow + i*64] = av.x;
            As[acol+1][arow + i*64] = av.y;
            As[acol+2][arow + i*64] = av.z;
            As[acol+3][arow + i*64] = av.w;
        }
        #pragma unroll
        for (int i = 0; i < 2; i++) {
            float4 bv = *reinterpret_cast<const float4*>(Bptr + (long)(k0 + i*8) * ldb);
            *reinterpret_cast<float4*>(&Bs[brow + i*8][bcol]) = bv;
        }
        __syncthreads();

        #pragma unroll
        for (int kk = 0; kk < BK; kk++) {
            float ar[8], br[8];
            #pragma unroll
            for (int i = 0; i < 2; i++) {
                float4 v = *reinterpret_cast<const float4*>(&As[kk][ty*8 + i*4]);
                ar[i*4+0]=v.x; ar[i*4+1]=v.y; ar[i*4+2]=v.z; ar[i*4+3]=v.w;
            }
            #pragma unroll
            for (int j = 0; j < 2; j++) {
                float4 v = *reinterpret_cast<const float4*>(&Bs[kk][tx*8 + j*4]);
                br[j*4+0]=v.x; br[j*4+1]=v.y; br[j*4+2]=v.z; br[j*4+3]=v.w;
            }
            #pragma unroll
            for (int i = 0; i < 8; i++)
                #pragma unroll
                for (int j = 0; j < 8; j++)
                    acc[i][j] += ar[i] * br[j];
        }
        __syncthreads();
    }

    #pragma unroll
    for (int i = 0; i < 8; i++) {
        long row = bm + ty*8 + i;
        #pragma unroll
        for (int j = 0; j < 2; j++) {
            int col = bn + tx*8 + j*4;
            float4 o;
            o.x = acc[i][j*4+0] + bias[col+0];
            o.y = acc[i][j*4+1] + bias[col+1];
            o.z = acc[i][j*4+2] + bias[col+2];
            o.w = acc[i][j*4+3] + bias[col+3];
            *reinterpret_cast<float4*>(C + row*ldc + col) = o;
        }
    }
}

// ------------- kc/vc = E^T @ {K,V}_head, then append bank rows --------------
// grid (2, H, B); block 256
__global__ __launch_bounds__(256) void kvcompress(
    const float* __restrict__ KV, const float* __restrict__ E_k,
    const float* __restrict__ E_v, const float* __restrict__ k_bank,
    const float* __restrict__ v_bank, float* __restrict__ kf,
    float* __restrict__ vf)
{
    int which = blockIdx.x;      // 0: K, 1: V
    int h = blockIdx.y, b = blockIdx.z;
    const float* E    = which ? E_v : E_k;
    const float* bank = which ? v_bank : k_bank;
    float* out = (which ? vf : kf) + ((long)(b*H_ + h) * L_) * D_;

    __shared__ float Es[64][64];
    __shared__ float Ks[64][64];

    int tid = threadIdx.x;
    int d  = tid & 63;
    int cg = tid >> 6;          // 0..3
    float acc[16];
    #pragma unroll
    for (int i = 0; i < 16; i++) acc[i] = 0.f;

    for (int s0 = 0; s0 < L_; s0 += 64) {
        // load E chunk [64 x 64]
        for (int i = tid*4; i < 64*64; i += 1024)
            *reinterpret_cast<float4*>(&Es[i>>6][i&63]) =
                *reinterpret_cast<const float4*>(E + (long)(s0 + (i>>6))*64 + (i&63));
        // load K/V head chunk [64 x 64]
        for (int i = tid; i < 64*16; i += 256) {
            int r = i >> 4, c4 = (i & 15)*4;
            *reinterpret_cast<float4*>(&Ks[r][c4]) =
                *reinterpret_cast<const float4*>(
                    KV + (long)b*L_*2*C_ + (long)(s0+r)*2*C_ + which*C_ + h*D_ + c4);
        }
        __syncthreads();
        for (int s = 0; s < 64; s++) {
            float kv = Ks[s][d];
            #pragma unroll
            for (int i = 0; i < 16; i++)
                acc[i] += Es[s][cg*16 + i] * kv;
        }
        __syncthreads();
    }
    #pragma unroll
    for (int i = 0; i < 16; i++)
        out[(long)(cg*16 + i)*D_ + d] = acc[i];

    // bank rows 64..127
    for (int i = tid; i < 64*64; i += 256) {
        int r = i >> 6, dd = i & 63;
        out[(long)(64 + r)*D_ + dd] = bank[(long)b*64*C_ + (long)r*C_ + h*D_ + dd];
    }
}

// ---------------- attention: 256 queries / block, 128 keys ------------------
// grid (N/256, H, B); block 256; dynamic smem 192KB
__global__ __launch_bounds__(256) void attn_kernel(
    const float* __restrict__ Q, const float* __restrict__ kf,
    const float* __restrict__ vf, float* __restrict__ O)
{
    extern __shared__ float sm[];
    float* ks = sm;                 // 128*64
    float* vs = sm + L_*D_;         // 128*64
    float* sc = sm + 2*L_*D_;       // 128*256

    int t = threadIdx.x;
    int qt = blockIdx.x, h = blockIdx.y, b = blockIdx.z;
    const float* kfp = kf + (long)(b*H_ + h) * L_ * D_;
    const float* vfp = vf + (long)(b*H_ + h) * L_ * D_;

    for (int i = t*4; i < L_*D_; i += 1024) {
        *reinterpret_cast<float4*>(&ks[i]) = *reinterpret_cast<const float4*>(&kfp[i]);
        *reinterpret_cast<float4*>(&vs[i]) = *reinterpret_cast<const float4*>(&vfp[i]);
    }

    long row = (long)b*N_ + qt*256 + t;
    const float* qp = Q + row*C_ + h*D_;
    float q[64];
    #pragma unroll
    for (int i = 0; i < 64; i += 4) {
        float4 v = *reinterpret_cast<const float4*>(qp + i);
        q[i]=v.x; q[i+1]=v.y; q[i+2]=v.z; q[i+3]=v.w;
    }
    __syncthreads();

    const float scale = 0.125f;     // 1/sqrt(64)
    float mx = -1e30f;
    for (int k = 0; k < L_; k++) {
        float s = 0.f;
        #pragma unroll
        for (int d = 0; d < 64; d += 4) {
            float4 kv = *reinterpret_cast<const float4*>(&ks[k*64 + d]);
            s += q[d]*kv.x + q[d+1]*kv.y + q[d+2]*kv.z + q[d+3]*kv.w;
        }
        s *= scale;
        sc[k*256 + t] = s;
        mx = fmaxf(mx, s);
    }
    float l = 0.f;
    for (int k = 0; k < L_; k++) {
        float e = expf(sc[k*256 + t] - mx);
        sc[k*256 + t] = e;
        l += e;
    }
    float o[64];
    #pragma unroll
    for (int i = 0; i < 64; i++) o[i] = 0.f;
    for (int k = 0; k < L_; k++) {
        float p = sc[k*256 + t];
        #pragma unroll
        for (int d = 0; d < 64; d += 4) {
            float4 vv = *reinterpret_cast<const float4*>(&vs[k*64 + d]);
            o[d]   += p*vv.x; o[d+1] += p*vv.y;
            o[d+2] += p*vv.z; o[d+3] += p*vv.w;
        }
    }
    float rl = 1.f / l;
    float* op = O + row*C_ + h*D_;
    #pragma unroll
    for (int d = 0; d < 64; d += 4) {
        float4 v;
        v.x = o[d]*rl; v.y = o[d+1]*rl; v.z = o[d+2]*rl; v.w = o[d+3]*rl;
        *reinterpret_cast<float4*>(op + d) = v;
    }
}

// ---------------------------------------------------------------------------
extern "C" void kernel_launch(void* const* d_in, const int* in_sizes, int n_in,
                              void* d_out, int out_size)
{
    const float* x      = (const float*)d_in[0];
    const float* Wqkv   = (const float*)d_in[1];
    const float* bqkv   = (const float*)d_in[2];
    const float* E_k    = (const float*)d_in[3];
    const float* E_v    = (const float*)d_in[4];
    const float* Wproj  = (const float*)d_in[5];
    const float* bproj  = (const float*)d_in[6];
    const float* k_bank = (const float*)d_in[7];
    const float* v_bank = (const float*)d_in[8];

    float *Q, *xp, *KV, *kf, *vf, *ao;
    cudaGetSymbolAddress((void**)&Q,  g_Q);
    cudaGetSymbolAddress((void**)&xp, g_xp);
    cudaGetSymbolAddress((void**)&KV, g_KV);
    cudaGetSymbolAddress((void**)&kf, g_kf);
    cudaGetSymbolAddress((void**)&vf, g_vf);
    cudaGetSymbolAddress((void**)&ao, g_ao);

    // 1) pooled tokens (first 128 only are ever used)
    pool_kernel<<<(B_*L_*C_/4 + 255)/256, 256>>>(x, xp);

    // 2) Q = x @ Wqkv[:,0:768] + bqkv[0:768]      (M=32768, N=768, K=768)
    sgemm128<<<dim3(C_/128, B_*N_/128), 256>>>(x, Wqkv, bqkv, Q,
                                               C_, C_, 3*C_, C_);

    // 3) KV = xp @ Wqkv[:,768:2304] + bqkv[768:]  (M=4096, N=1536, K=768)
    sgemm128<<<dim3(2*C_/128, B_*L_/128), 256>>>(xp, Wqkv + C_, bqkv + C_, KV,
                                                 C_, C_, 3*C_, 2*C_);

    // 4) compress + bank concat
    kvcompress<<<dim3(2, H_, B_), 256>>>(KV, E_k, E_v, k_bank, v_bank, kf, vf);

    // 5) attention
    cudaFuncSetAttribute(attn_kernel,
                         cudaFuncAttributeMaxDynamicSharedMemorySize, 196608);
    attn_kernel<<<dim3(N_/256, H_, B_), 256, 196608>>>(Q, kf, vf, ao);

    // 6) out = ao @ Wproj + bproj                 (M=32768, N=768, K=768)
    sgemm128<<<dim3(C_/128, B_*N_/128), 256>>>(ao, Wproj, bproj, (float*)d_out,
                                               C_, C_, C_, C_);
}

// round 2
// speedup vs baseline: 1.9357x; 1.9357x over previous
#include <cuda_runtime.h>
#include <math.h>
#include <stdint.h>

#define B_  32
#define N_  1024
#define C_  768
#define H_  12
#define D_  64
#define L_  128

// ---------------- scratch (device globals: no allocations allowed) ----------
__device__ float g_Q [B_*N_*C_];        // Q projection (B,N,C)
__device__ float g_xp[B_*L_*C_];        // pooled first-128 tokens
__device__ float g_KV[B_*L_*2*C_];      // K|V projections of pooled tokens
__device__ float g_kf[B_*H_*L_*D_];     // k_full (B,H,128,64)
__device__ float g_vf[B_*H_*L_*D_];     // v_full
__device__ float g_ao[B_*N_*C_];        // attention output (B,N,C)

__device__ __forceinline__ unsigned f2tf(float f) {
    unsigned u;
    asm("cvt.rna.tf32.f32 %0, %1;" : "=r"(u) : "f"(f));
    return u;
}

// ---------------- pooling: xp[b,p,c] = 0.5*(x[b,2p,c]+x[b,2p+1,c]) ----------
__global__ void pool_kernel(const float* __restrict__ x, float* __restrict__ xp)
{
    int i = blockIdx.x * blockDim.x + threadIdx.x;      // float4 index
    const int TOT4 = B_*L_*C_/4;
    if (i >= TOT4) return;
    int c4 = i % (C_/4);
    int p  = (i / (C_/4)) % L_;
    int b  = i / (C_/4 * L_);
    long base = (long)b*N_*C_ + (long)(2*p)*C_ + c4*4;
    float4 a = *reinterpret_cast<const float4*>(x + base);
    float4 c = *reinterpret_cast<const float4*>(x + base + C_);
    float4 o;
    o.x = 0.5f*(a.x+c.x); o.y = 0.5f*(a.y+c.y);
    o.z = 0.5f*(a.z+c.z); o.w = 0.5f*(a.w+c.w);
    *reinterpret_cast<float4*>(xp + (long)i*4) = o;
}

// ---------------- tf32 tensor-core GEMM: C = A*B + bias ---------------------
// 128x128 tile, BK=32, 256 threads (8 warps: 2 x 4), warp tile 64x32.
// mma.sync.aligned.m16n8k8.row.col.f32.tf32.tf32.f32
__global__ __launch_bounds__(256) void sgemm_tf32(
    const float* __restrict__ A, const float* __restrict__ Bm,
    const float* __restrict__ bias, float* __restrict__ C,
    int K, int lda, int ldb, int ldc)
{
    __shared__ uint32_t As[128][36];   // [m][k], pad 4
    __shared__ uint32_t Bs[32][132];   // [k][n], pad 4

    const int t    = threadIdx.x;
    const int warp = t >> 5;
    const int lane = t & 31;
    const int group = lane >> 2;       // 0..7
    const int tid4  = lane & 3;        // 0..3
    const int wm = (warp & 1) * 64;    // warp row base in tile
    const int wn = (warp >> 1) * 32;   // warp col base in tile

    const int bm = blockIdx.y * 128, bn = blockIdx.x * 128;

    const int am  = t >> 3;            // 0..31 (+i*32)
    const int ak4 = (t & 7) * 4;       // 0..28
    const int bk  = t >> 5;            // 0..7 (+i*8)
    const int bn4 = (t & 31) * 4;      // 0..124

    float acc[4][4][4];
    #pragma unroll
    for (int mf = 0; mf < 4; mf++)
        #pragma unroll
        for (int nf = 0; nf < 4; nf++)
            #pragma unroll
            for (int r = 0; r < 4; r++) acc[mf][nf][r] = 0.f;

    for (int k0 = 0; k0 < K; k0 += 32) {
        // A tile 128x32 -> tf32
        #pragma unroll
        for (int i = 0; i < 4; i++) {
            int m = am + i*32;
            float4 v = *reinterpret_cast<const float4*>(
                A + (long)(bm + m)*lda + k0 + ak4);
            As[m][ak4+0] = f2tf(v.x); As[m][ak4+1] = f2tf(v.y);
            As[m][ak4+2] = f2tf(v.z); As[m][ak4+3] = f2tf(v.w);
        }
        // B tile 32x128 -> tf32
        #pragma unroll
        for (int i = 0; i < 4; i++) {
            int k = bk + i*8;
            float4 v = *reinterpret_cast<const float4*>(
                Bm + (long)(k0 + k)*ldb + bn + bn4);
            Bs[k][bn4+0] = f2tf(v.x); Bs[k][bn4+1] = f2tf(v.y);
            Bs[k][bn4+2] = f2tf(v.z); Bs[k][bn4+3] = f2tf(v.w);
        }
        __syncthreads();

        #pragma unroll
        for (int ks = 0; ks < 4; ks++) {
            const int kk = ks * 8;
            uint32_t a[4][4], b[4][2];
            #pragma unroll
            for (int mf = 0; mf < 4; mf++) {
                int r0 = wm + mf*16 + group;
                a[mf][0] = As[r0    ][kk + tid4];
                a[mf][1] = As[r0 + 8][kk + tid4];
                a[mf][2] = As[r0    ][kk + tid4 + 4];
                a[mf][3] = As[r0 + 8][kk + tid4 + 4];
            }
            #pragma unroll
            for (int nf = 0; nf < 4; nf++) {
                int cc = wn + nf*8 + group;
                b[nf][0] = Bs[kk + tid4    ][cc];
                b[nf][1] = Bs[kk + tid4 + 4][cc];
            }
            #pragma unroll
            for (int mf = 0; mf < 4; mf++)
                #pragma unroll
                for (int nf = 0; nf < 4; nf++) {
                    asm volatile(
                        "mma.sync.aligned.m16n8k8.row.col.f32.tf32.tf32.f32 "
                        "{%0,%1,%2,%3}, {%4,%5,%6,%7}, {%8,%9}, {%0,%1,%2,%3};"
                        : "+f"(acc[mf][nf][0]), "+f"(acc[mf][nf][1]),
                          "+f"(acc[mf][nf][2]), "+f"(acc[mf][nf][3])
                        : "r"(a[mf][0]), "r"(a[mf][1]),
                          "r"(a[mf][2]), "r"(a[mf][3]),
                          "r"(b[nf][0]), "r"(b[nf][1]));
                }
        }
        __syncthreads();
    }

    // epilogue: bias add, float2 stores
    #pragma unroll
    for (int mf = 0; mf < 4; mf++) {
        int r0 = bm + wm + mf*16 + group;
        #pragma unroll
        for (int nf = 0; nf < 4; nf++) {
            int c0 = bn + wn + nf*8 + tid4*2;
            float2 bi = *reinterpret_cast<const float2*>(bias + c0);
            float2 o0, o1;
            o0.x = acc[mf][nf][0] + bi.x; o0.y = acc[mf][nf][1] + bi.y;
            o1.x = acc[mf][nf][2] + bi.x; o1.y = acc[mf][nf][3] + bi.y;
            *reinterpret_cast<float2*>(C + (long)r0*ldc + c0) = o0;
            *reinterpret_cast<float2*>(C + (long)(r0+8)*ldc + c0) = o1;
        }
    }
}

// ------------- kc/vc = E^T @ {K,V}_head, then append bank rows --------------
__global__ __launch_bounds__(256) void kvcompress(
    const float* __restrict__ KV, const float* __restrict__ E_k,
    const float* __restrict__ E_v, const float* __restrict__ k_bank,
    const float* __restrict__ v_bank, float* __restrict__ kf,
    float* __restrict__ vf)
{
    int which = blockIdx.x;      // 0: K, 1: V
    int h = blockIdx.y, b = blockIdx.z;
    const float* E    = which ? E_v : E_k;
    const float* bank = which ? v_bank : k_bank;
    float* out = (which ? vf : kf) + ((long)(b*H_ + h) * L_) * D_;

    __shared__ float Es[64][64];
    __shared__ float Ks[64][64];

    int tid = threadIdx.x;
    int d  = tid & 63;
    int cg = tid >> 6;          // 0..3
    float acc[16];
    #pragma unroll
    for (int i = 0; i < 16; i++) acc[i] = 0.f;

    for (int s0 = 0; s0 < L_; s0 += 64) {
        for (int i = tid*4; i < 64*64; i += 1024)
            *reinterpret_cast<float4*>(&Es[i>>6][i&63]) =
                *reinterpret_cast<const float4*>(E + (long)(s0 + (i>>6))*64 + (i&63));
        for (int i = tid; i < 64*16; i += 256) {
            int r = i >> 4, c4 = (i & 15)*4;
            *reinterpret_cast<float4*>(&Ks[r][c4]) =
                *reinterpret_cast<const float4*>(
                    KV + (long)b*L_*2*C_ + (long)(s0+r)*2*C_ + which*C_ + h*D_ + c4);
        }
        __syncthreads();
        for (int s = 0; s < 64; s++) {
            float kv = Ks[s][d];
            #pragma unroll
            for (int i = 0; i < 16; i++)
                acc[i] += Es[s][cg*16 + i] * kv;
        }
        __syncthreads();
    }
    #pragma unroll
    for (int i = 0; i < 16; i++)
        out[(long)(cg*16 + i)*D_ + d] = acc[i];

    for (int i = tid; i < 64*64; i += 256) {
        int r = i >> 6, dd = i & 63;
        out[(long)(64 + r)*D_ + dd] = bank[(long)b*64*C_ + (long)r*C_ + h*D_ + dd];
    }
}

// ---------------- attention: 256 queries / block, 128 keys ------------------
__global__ __launch_bounds__(256) void attn_kernel(
    const float* __restrict__ Q, const float* __restrict__ kf,
    const float* __restrict__ vf, float* __restrict__ O)
{
    extern __shared__ float sm[];
    float* ks = sm;                 // 128*64
    float* vs = sm + L_*D_;         // 128*64
    float* sc = sm + 2*L_*D_;       // 128*256

    int t = threadIdx.x;
    int qt = blockIdx.x, h = blockIdx.y, b = blockIdx.z;
    const float* kfp = kf + (long)(b*H_ + h) * L_ * D_;
    const float* vfp = vf + (long)(b*H_ + h) * L_ * D_;

    for (int i = t*4; i < L_*D_; i += 1024) {
        *reinterpret_cast<float4*>(&ks[i]) = *reinterpret_cast<const float4*>(&kfp[i]);
        *reinterpret_cast<float4*>(&vs[i]) = *reinterpret_cast<const float4*>(&vfp[i]);
    }

    long row = (long)b*N_ + qt*256 + t;
    const float* qp = Q + row*C_ + h*D_;
    float q[64];
    #pragma unroll
    for (int i = 0; i < 64; i += 4) {
        float4 v = *reinterpret_cast<const float4*>(qp + i);
        q[i]=v.x; q[i+1]=v.y; q[i+2]=v.z; q[i+3]=v.w;
    }
    __syncthreads();

    const float scale = 0.125f;
    float mx = -1e30f;
    for (int k = 0; k < L_; k++) {
        float s = 0.f;
        #pragma unroll
        for (int d = 0; d < 64; d += 4) {
            float4 kv = *reinterpret_cast<const float4*>(&ks[k*64 + d]);
            s += q[d]*kv.x + q[d+1]*kv.y + q[d+2]*kv.z + q[d+3]*kv.w;
        }
        s *= scale;
        sc[k*256 + t] = s;
        mx = fmaxf(mx, s);
    }
    float l = 0.f;
    for (int k = 0; k < L_; k++) {
        float e = expf(sc[k*256 + t] - mx);
        sc[k*256 + t] = e;
        l += e;
    }
    float o[64];
    #pragma unroll
    for (int i = 0; i < 64; i++) o[i] = 0.f;
    for (int k = 0; k < L_; k++) {
        float p = sc[k*256 + t];
        #pragma unroll
        for (int d = 0; d < 64; d += 4) {
            float4 vv = *reinterpret_cast<const float4*>(&vs[k*64 + d]);
            o[d]   += p*vv.x; o[d+1] += p*vv.y;
            o[d+2] += p*vv.z; o[d+3] += p*vv.w;
        }
    }
    float rl = 1.f / l;
    float* op = O + row*C_ + h*D_;
    #pragma unroll
    for (int d = 0; d < 64; d += 4) {
        float4 v;
        v.x = o[d]*rl; v.y = o[d+1]*rl; v.z = o[d+2]*rl; v.w = o[d+3]*rl;
        *reinterpret_cast<float4*>(op + d) = v;
    }
}

// ---------------------------------------------------------------------------
extern "C" void kernel_launch(void* const* d_in, const int* in_sizes, int n_in,
                              void* d_out, int out_size)
{
    const float* x      = (const float*)d_in[0];
    const float* Wqkv   = (const float*)d_in[1];
    const float* bqkv   = (const float*)d_in[2];
    const float* E_k    = (const float*)d_in[3];
    const float* E_v    = (const float*)d_in[4];
    const float* Wproj  = (const float*)d_in[5];
    const float* bproj  = (const float*)d_in[6];
    const float* k_bank = (const float*)d_in[7];
    const float* v_bank = (const float*)d_in[8];

    float *Q, *xp, *KV, *kf, *vf, *ao;
    cudaGetSymbolAddress((void**)&Q,  g_Q);
    cudaGetSymbolAddress((void**)&xp, g_xp);
    cudaGetSymbolAddress((void**)&KV, g_KV);
    cudaGetSymbolAddress((void**)&kf, g_kf);
    cudaGetSymbolAddress((void**)&vf, g_vf);
    cudaGetSymbolAddress((void**)&ao, g_ao);

    // 1) pooled tokens (first 128 only are ever used)
    pool_kernel<<<(B_*L_*C_/4 + 255)/256, 256>>>(x, xp);

    // 2) Q = x @ Wqkv[:,0:768] + bqkv[0:768]      (M=32768, N=768, K=768)
    sgemm_tf32<<<dim3(C_/128, B_*N_/128), 256>>>(x, Wqkv, bqkv, Q,
                                                 C_, C_, 3*C_, C_);

    // 3) KV = xp @ Wqkv[:,768:2304] + bqkv[768:]  (M=4096, N=1536, K=768)
    sgemm_tf32<<<dim3(2*C_/128, B_*L_/128), 256>>>(xp, Wqkv + C_, bqkv + C_, KV,
                                                   C_, C_, 3*C_, 2*C_);

    // 4) compress + bank concat
    kvcompress<<<dim3(2, H_, B_), 256>>>(KV, E_k, E_v, k_bank, v_bank, kf, vf);

    // 5) attention
    cudaFuncSetAttribute(attn_kernel,
                         cudaFuncAttributeMaxDynamicSharedMemorySize, 196608);
    attn_kernel<<<dim3(N_/256, H_, B_), 256, 196608>>>(Q, kf, vf, ao);

    // 6) out = ao @ Wproj + bproj                 (M=32768, N=768, K=768)
    sgemm_tf32<<<dim3(C_/128, B_*N_/128), 256>>>(ao, Wproj, bproj, (float*)d_out,
                                                 C_, C_, C_, C_);
}

// round 3
// speedup vs baseline: 2.4354x; 1.2582x over previous
#include <cuda_runtime.h>
#include <math.h>
#include <stdint.h>

#define B_  32
#define N_  1024
#define C_  768
#define H_  12
#define D_  64
#define L_  128

// ---------------- scratch (device globals: no allocations allowed) ----------
__device__ float g_Q [B_*N_*C_];        // Q projection (B,N,C)
__device__ float g_xp[B_*L_*C_];        // pooled first-128 tokens
__device__ float g_KV[B_*L_*2*C_];      // K|V projections of pooled tokens
__device__ float g_kf[B_*H_*L_*D_];     // k_full (B,H,128,64)
__device__ float g_vf[B_*H_*L_*D_];     // v_full
__device__ float g_ao[B_*N_*C_];        // attention output (B,N,C)

__device__ __forceinline__ unsigned f2tf(float f) {
    unsigned u;
    asm("cvt.rna.tf32.f32 %0, %1;" : "=r"(u) : "f"(f));
    return u;
}

__device__ __forceinline__ void mma_tf32(
    float* c, uint32_t a0, uint32_t a1, uint32_t a2, uint32_t a3,
    uint32_t b0, uint32_t b1)
{
    asm volatile(
        "mma.sync.aligned.m16n8k8.row.col.f32.tf32.tf32.f32 "
        "{%0,%1,%2,%3}, {%4,%5,%6,%7}, {%8,%9}, {%0,%1,%2,%3};"
        : "+f"(c[0]), "+f"(c[1]), "+f"(c[2]), "+f"(c[3])
        : "r"(a0), "r"(a1), "r"(a2), "r"(a3), "r"(b0), "r"(b1));
}

// ---------------- pooling: xp[b,p,c] = 0.5*(x[b,2p,c]+x[b,2p+1,c]) ----------
__global__ void pool_kernel(const float* __restrict__ x, float* __restrict__ xp)
{
    int i = blockIdx.x * blockDim.x + threadIdx.x;      // float4 index
    const int TOT4 = B_*L_*C_/4;
    if (i >= TOT4) return;
    int c4 = i % (C_/4);
    int p  = (i / (C_/4)) % L_;
    int b  = i / (C_/4 * L_);
    long base = (long)b*N_*C_ + (long)(2*p)*C_ + c4*4;
    float4 a = *reinterpret_cast<const float4*>(x + base);
    float4 c = *reinterpret_cast<const float4*>(x + base + C_);
    float4 o;
    o.x = 0.5f*(a.x+c.x); o.y = 0.5f*(a.y+c.y);
    o.z = 0.5f*(a.z+c.z); o.w = 0.5f*(a.w+c.w);
    *reinterpret_cast<float4*>(xp + (long)i*4) = o;
}

// ---------------- tf32 tensor-core GEMM: C = A*B + bias ---------------------
__global__ __launch_bounds__(256) void sgemm_tf32(
    const float* __restrict__ A, const float* __restrict__ Bm,
    const float* __restrict__ bias, float* __restrict__ C,
    int K, int lda, int ldb, int ldc)
{
    __shared__ uint32_t As[128][36];   // [m][k], pad 4
    __shared__ uint32_t Bs[32][132];   // [k][n], pad 4

    const int t    = threadIdx.x;
    const int warp = t >> 5;
    const int lane = t & 31;
    const int group = lane >> 2;       // 0..7
    const int tid4  = lane & 3;        // 0..3
    const int wm = (warp & 1) * 64;
    const int wn = (warp >> 1) * 32;

    const int bm = blockIdx.y * 128, bn = blockIdx.x * 128;

    const int am  = t >> 3;
    const int ak4 = (t & 7) * 4;
    const int bk  = t >> 5;
    const int bn4 = (t & 31) * 4;

    float acc[4][4][4];
    #pragma unroll
    for (int mf = 0; mf < 4; mf++)
        #pragma unroll
        for (int nf = 0; nf < 4; nf++)
            #pragma unroll
            for (int r = 0; r < 4; r++) acc[mf][nf][r] = 0.f;

    for (int k0 = 0; k0 < K; k0 += 32) {
        #pragma unroll
        for (int i = 0; i < 4; i++) {
            int m = am + i*32;
            float4 v = *reinterpret_cast<const float4*>(
                A + (long)(bm + m)*lda + k0 + ak4);
            As[m][ak4+0] = f2tf(v.x); As[m][ak4+1] = f2tf(v.y);
            As[m][ak4+2] = f2tf(v.z); As[m][ak4+3] = f2tf(v.w);
        }
        #pragma unroll
        for (int i = 0; i < 4; i++) {
            int k = bk + i*8;
            float4 v = *reinterpret_cast<const float4*>(
                Bm + (long)(k0 + k)*ldb + bn + bn4);
            Bs[k][bn4+0] = f2tf(v.x); Bs[k][bn4+1] = f2tf(v.y);
            Bs[k][bn4+2] = f2tf(v.z); Bs[k][bn4+3] = f2tf(v.w);
        }
        __syncthreads();

        #pragma unroll
        for (int ks = 0; ks < 4; ks++) {
            const int kk = ks * 8;
            uint32_t a[4][4], b[4][2];
            #pragma unroll
            for (int mf = 0; mf < 4; mf++) {
                int r0 = wm + mf*16 + group;
                a[mf][0] = As[r0    ][kk + tid4];
                a[mf][1] = As[r0 + 8][kk + tid4];
                a[mf][2] = As[r0    ][kk + tid4 + 4];
                a[mf][3] = As[r0 + 8][kk + tid4 + 4];
            }
            #pragma unroll
            for (int nf = 0; nf < 4; nf++) {
                int cc = wn + nf*8 + group;
                b[nf][0] = Bs[kk + tid4    ][cc];
                b[nf][1] = Bs[kk + tid4 + 4][cc];
            }
            #pragma unroll
            for (int mf = 0; mf < 4; mf++)
                #pragma unroll
                for (int nf = 0; nf < 4; nf++)
                    mma_tf32(acc[mf][nf], a[mf][0], a[mf][1], a[mf][2], a[mf][3],
                             b[nf][0], b[nf][1]);
        }
        __syncthreads();
    }

    #pragma unroll
    for (int mf = 0; mf < 4; mf++) {
        int r0 = bm + wm + mf*16 + group;
        #pragma unroll
        for (int nf = 0; nf < 4; nf++) {
            int c0 = bn + wn + nf*8 + tid4*2;
            float2 bi = *reinterpret_cast<const float2*>(bias + c0);
            float2 o0, o1;
            o0.x = acc[mf][nf][0] + bi.x; o0.y = acc[mf][nf][1] + bi.y;
            o1.x = acc[mf][nf][2] + bi.x; o1.y = acc[mf][nf][3] + bi.y;
            *reinterpret_cast<float2*>(C + (long)r0*ldc + c0) = o0;
            *reinterpret_cast<float2*>(C + (long)(r0+8)*ldc + c0) = o1;
        }
    }
}

// ------------- kc/vc = E^T @ {K,V}_head, then append bank rows --------------
__global__ __launch_bounds__(256) void kvcompress(
    const float* __restrict__ KV, const float* __restrict__ E_k,
    const float* __restrict__ E_v, const float* __restrict__ k_bank,
    const float* __restrict__ v_bank, float* __restrict__ kf,
    float* __restrict__ vf)
{
    int which = blockIdx.x;      // 0: K, 1: V
    int h = blockIdx.y, b = blockIdx.z;
    const float* E    = which ? E_v : E_k;
    const float* bank = which ? v_bank : k_bank;
    float* out = (which ? vf : kf) + ((long)(b*H_ + h) * L_) * D_;

    __shared__ float Es[64][64];
    __shared__ float Ks[64][64];

    int tid = threadIdx.x;
    int d  = tid & 63;
    int cg = tid >> 6;
    float acc[16];
    #pragma unroll
    for (int i = 0; i < 16; i++) acc[i] = 0.f;

    for (int s0 = 0; s0 < L_; s0 += 64) {
        for (int i = tid*4; i < 64*64; i += 1024)
            *reinterpret_cast<float4*>(&Es[i>>6][i&63]) =
                *reinterpret_cast<const float4*>(E + (long)(s0 + (i>>6))*64 + (i&63));
        for (int i = tid; i < 64*16; i += 256) {
            int r = i >> 4, c4 = (i & 15)*4;
            *reinterpret_cast<float4*>(&Ks[r][c4]) =
                *reinterpret_cast<const float4*>(
                    KV + (long)b*L_*2*C_ + (long)(s0+r)*2*C_ + which*C_ + h*D_ + c4);
        }
        __syncthreads();
        for (int s = 0; s < 64; s++) {
            float kv = Ks[s][d];
            #pragma unroll
            for (int i = 0; i < 16; i++)
                acc[i] += Es[s][cg*16 + i] * kv;
        }
        __syncthreads();
    }
    #pragma unroll
    for (int i = 0; i < 16; i++)
        out[(long)(cg*16 + i)*D_ + d] = acc[i];

    for (int i = tid; i < 64*64; i += 256) {
        int r = i >> 6, dd = i & 63;
        out[(long)(64 + r)*D_ + dd] = bank[(long)b*64*C_ + (long)r*C_ + h*D_ + dd];
    }
}

// -------- tensor-core attention: 128 queries/block, 128 keys, tf32 ----------
// grid (N/128, H, B); block 256 (8 warps); warp = 16 queries
// smem: Ks[128][68], Vt[64][132], Ps[128][132], Qs[128][68] (tf32 words)
#define KS_STRIDE 68
#define VT_STRIDE 132
#define PS_STRIDE 132
#define ATTN_SMEM ((128*68 + 64*132 + 128*132 + 128*68) * 4)

__global__ __launch_bounds__(256) void attn_tc(
    const float* __restrict__ Q, const float* __restrict__ kf,
    const float* __restrict__ vf, float* __restrict__ O)
{
    extern __shared__ uint32_t smu[];
    uint32_t* Ks = smu;                       // [128][68]
    uint32_t* Vt = Ks + 128*KS_STRIDE;        // [64][132]
    uint32_t* Ps = Vt + 64*VT_STRIDE;         // [128][132]
    uint32_t* Qs = Ps + 128*PS_STRIDE;        // [128][68]

    const int t = threadIdx.x;
    const int warp = t >> 5, lane = t & 31;
    const int group = lane >> 2, tid4 = lane & 3;
    const int qb = blockIdx.x, h = blockIdx.y, b = blockIdx.z;

    const float* kfp = kf + (long)(b*H_ + h) * L_ * D_;
    const float* vfp = vf + (long)(b*H_ + h) * L_ * D_;

    // --- load K (tf32) ---
    for (int i = t*4; i < L_*D_; i += 1024) {
        float4 v = *reinterpret_cast<const float4*>(kfp + i);
        int k = i >> 6, d = i & 63;
        uint32_t* dst = &Ks[k*KS_STRIDE + d];
        dst[0]=f2tf(v.x); dst[1]=f2tf(v.y); dst[2]=f2tf(v.z); dst[3]=f2tf(v.w);
    }
    // --- load V transposed (tf32): Vt[d][k] ---
    {
        int k = t & 127;
        int d0 = (t >> 7) * 32;
        #pragma unroll
        for (int d = 0; d < 32; d += 4) {
            float4 v = *reinterpret_cast<const float4*>(vfp + k*64 + d0 + d);
            Vt[(d0+d+0)*VT_STRIDE + k] = f2tf(v.x);
            Vt[(d0+d+1)*VT_STRIDE + k] = f2tf(v.y);
            Vt[(d0+d+2)*VT_STRIDE + k] = f2tf(v.z);
            Vt[(d0+d+3)*VT_STRIDE + k] = f2tf(v.w);
        }
    }
    // --- load Q head slice (tf32): Qs[q][d] ---
    {
        long base = ((long)b*N_ + qb*128) * C_ + h*D_;
        for (int i = t*4; i < 128*64; i += 1024) {
            int q = i >> 6, d = i & 63;
            float4 v = *reinterpret_cast<const float4*>(Q + base + (long)q*C_ + d);
            uint32_t* dst = &Qs[q*KS_STRIDE + d];
            dst[0]=f2tf(v.x); dst[1]=f2tf(v.y); dst[2]=f2tf(v.z); dst[3]=f2tf(v.w);
        }
    }
    __syncthreads();

    // --- S = Q K^T (warp: rows warp*16..+15, all 128 keys) ---
    float accS[16][4];
    #pragma unroll
    for (int nt = 0; nt < 16; nt++)
        #pragma unroll
        for (int r = 0; r < 4; r++) accS[nt][r] = 0.f;

    const int qrow = warp*16;
    #pragma unroll
    for (int kf8 = 0; kf8 < 8; kf8++) {
        const int kk = kf8*8;
        uint32_t a0 = Qs[(qrow+group  )*KS_STRIDE + kk + tid4];
        uint32_t a1 = Qs[(qrow+group+8)*KS_STRIDE + kk + tid4];
        uint32_t a2 = Qs[(qrow+group  )*KS_STRIDE + kk + tid4 + 4];
        uint32_t a3 = Qs[(qrow+group+8)*KS_STRIDE + kk + tid4 + 4];
        #pragma unroll
        for (int nt = 0; nt < 16; nt++) {
            uint32_t b0 = Ks[(nt*8+group)*KS_STRIDE + kk + tid4];
            uint32_t b1 = Ks[(nt*8+group)*KS_STRIDE + kk + tid4 + 4];
            mma_tf32(accS[nt], a0, a1, a2, a3, b0, b1);
        }
    }

    // --- softmax over 128 keys (rows group, group+8 within warp tile) ---
    const float scale = 0.125f;
    float m0 = -1e30f, m1 = -1e30f;
    #pragma unroll
    for (int nt = 0; nt < 16; nt++) {
        accS[nt][0] *= scale; accS[nt][1] *= scale;
        accS[nt][2] *= scale; accS[nt][3] *= scale;
        m0 = fmaxf(m0, fmaxf(accS[nt][0], accS[nt][1]));
        m1 = fmaxf(m1, fmaxf(accS[nt][2], accS[nt][3]));
    }
    m0 = fmaxf(m0, __shfl_xor_sync(0xffffffff, m0, 1));
    m0 = fmaxf(m0, __shfl_xor_sync(0xffffffff, m0, 2));
    m1 = fmaxf(m1, __shfl_xor_sync(0xffffffff, m1, 1));
    m1 = fmaxf(m1, __shfl_xor_sync(0xffffffff, m1, 2));

    float l0 = 0.f, l1 = 0.f;
    #pragma unroll
    for (int nt = 0; nt < 16; nt++) {
        accS[nt][0] = expf(accS[nt][0] - m0);
        accS[nt][1] = expf(accS[nt][1] - m0);
        accS[nt][2] = expf(accS[nt][2] - m1);
        accS[nt][3] = expf(accS[nt][3] - m1);
        l0 += accS[nt][0] + accS[nt][1];
        l1 += accS[nt][2] + accS[nt][3];
    }
    l0 += __shfl_xor_sync(0xffffffff, l0, 1);
    l0 += __shfl_xor_sync(0xffffffff, l0, 2);
    l1 += __shfl_xor_sync(0xffffffff, l1, 1);
    l1 += __shfl_xor_sync(0xffffffff, l1, 2);
    float rl0 = 1.f / l0, rl1 = 1.f / l1;

    // --- store P (already normalized) as tf32 ---
    #pragma unroll
    for (int nt = 0; nt < 16; nt++) {
        int col = nt*8 + tid4*2;
        uint2 p0, p1;
        p0.x = f2tf(accS[nt][0]*rl0); p0.y = f2tf(accS[nt][1]*rl0);
        p1.x = f2tf(accS[nt][2]*rl1); p1.y = f2tf(accS[nt][3]*rl1);
        *reinterpret_cast<uint2*>(&Ps[(qrow+group  )*PS_STRIDE + col]) = p0;
        *reinterpret_cast<uint2*>(&Ps[(qrow+group+8)*PS_STRIDE + col]) = p1;
    }
    __syncwarp();

    // --- O = P V (k-dim = 128 keys, n-dim = 64 d) ---
    float accO[8][4];
    #pragma unroll
    for (int nt = 0; nt < 8; nt++)
        #pragma unroll
        for (int r = 0; r < 4; r++) accO[nt][r] = 0.f;

    #pragma unroll
    for (int kf8 = 0; kf8 < 16; kf8++) {
        const int kk = kf8*8;
        uint32_t a0 = Ps[(qrow+group  )*PS_STRIDE + kk + tid4];
        uint32_t a1 = Ps[(qrow+group+8)*PS_STRIDE + kk + tid4];
        uint32_t a2 = Ps[(qrow+group  )*PS_STRIDE + kk + tid4 + 4];
        uint32_t a3 = Ps[(qrow+group+8)*PS_STRIDE + kk + tid4 + 4];
        #pragma unroll
        for (int nt = 0; nt < 8; nt++) {
            uint32_t b0 = Vt[(nt*8+group)*VT_STRIDE + kk + tid4];
            uint32_t b1 = Vt[(nt*8+group)*VT_STRIDE + kk + tid4 + 4];
            mma_tf32(accO[nt], a0, a1, a2, a3, b0, b1);
        }
    }

    // --- epilogue ---
    long row0 = (long)b*N_ + qb*128 + qrow + group;
    #pragma unroll
    for (int nt = 0; nt < 8; nt++) {
        int col = h*D_ + nt*8 + tid4*2;
        float2 o0, o1;
        o0.x = accO[nt][0]; o0.y = accO[nt][1];
        o1.x = accO[nt][2]; o1.y = accO[nt][3];
        *reinterpret_cast<float2*>(O + row0*C_ + col) = o0;
        *reinterpret_cast<float2*>(O + (row0+8)*C_ + col) = o1;
    }
}

// ---------------------------------------------------------------------------
extern "C" void kernel_launch(void* const* d_in, const int* in_sizes, int n_in,
                              void* d_out, int out_size)
{
    const float* x      = (const float*)d_in[0];
    const float* Wqkv   = (const float*)d_in[1];
    const float* bqkv   = (const float*)d_in[2];
    const float* E_k    = (const float*)d_in[3];
    const float* E_v    = (const float*)d_in[4];
    const float* Wproj  = (const float*)d_in[5];
    const float* bproj  = (const float*)d_in[6];
    const float* k_bank = (const float*)d_in[7];
    const float* v_bank = (const float*)d_in[8];

    float *Q, *xp, *KV, *kf, *vf, *ao;
    cudaGetSymbolAddress((void**)&Q,  g_Q);
    cudaGetSymbolAddress((void**)&xp, g_xp);
    cudaGetSymbolAddress((void**)&KV, g_KV);
    cudaGetSymbolAddress((void**)&kf, g_kf);
    cudaGetSymbolAddress((void**)&vf, g_vf);
    cudaGetSymbolAddress((void**)&ao, g_ao);

    // 1) pooled tokens (first 128 only are ever used)
    pool_kernel<<<(B_*L_*C_/4 + 255)/256, 256>>>(x, xp);

    // 2) Q = x @ Wqkv[:,0:768] + bqkv[0:768]
    sgemm_tf32<<<dim3(C_/128, B_*N_/128), 256>>>(x, Wqkv, bqkv, Q,
                                                 C_, C_, 3*C_, C_);

    // 3) KV = xp @ Wqkv[:,768:2304] + bqkv[768:]
    sgemm_tf32<<<dim3(2*C_/128, B_*L_/128), 256>>>(xp, Wqkv + C_, bqkv + C_, KV,
                                                   C_, C_, 3*C_, 2*C_);

    // 4) compress + bank concat
    kvcompress<<<dim3(2, H_, B_), 256>>>(KV, E_k, E_v, k_bank, v_bank, kf, vf);

    // 5) tensor-core attention
    cudaFuncSetAttribute(attn_tc,
                         cudaFuncAttributeMaxDynamicSharedMemorySize, ATTN_SMEM);
    attn_tc<<<dim3(N_/128, H_, B_), 256, ATTN_SMEM>>>(Q, kf, vf, ao);

    // 6) out = ao @ Wproj + bproj
    sgemm_tf32<<<dim3(C_/128, B_*N_/128), 256>>>(ao, Wproj, bproj, (float*)d_out,
                                                 C_, C_, C_, C_);
}